// round 15
// baseline (speedup 1.0000x reference)
#include <cuda_runtime.h>
#include <cuda_fp16.h>
#include <cstdint>

// GCN layer: out = segment_mean( (h @ W^T)[src], dst )
//   h [100000,256] f32, W [128,256] f32, src/dst [1.6M] idx (dtype runtime-detected)
// fp16 single-pass HMMA GEMM (f32 accum) + fp16 z; CSR build overlapped with GEMM.
// This round: 16-slot cp.async pipelined gather (fixed ring) + parallel detect.

#define IN_F  256
#define OUT_F 128
#define MAX_NODES 100000
#define MAX_EDGES 1600000
#define SCAN_BLK  1024
#define GDEPTH 8            // rows in flight per warp
#define GSLOTS 16           // ring slots per warp (2x depth: no slot collision)

__device__ __half   g_z16[(size_t)MAX_NODES * OUT_F];
__device__ int      g_count[MAX_NODES];
__device__ int      g_off[MAX_NODES];
__device__ int      g_cur[MAX_NODES];
__device__ int      g_srcs[MAX_EDGES];
__device__ int      g_blksum[(MAX_NODES + SCAN_BLK - 1) / SCAN_BLK + 1];
__device__ int      g_idx_is64;
__device__ unsigned g_Wh[OUT_F * IN_F / 2];   // W fp16 plane (packed f16x2)

static cudaStream_t g_s2;
static cudaEvent_t  g_evFork, g_evJoin;
static struct _StreamInit {
    _StreamInit() {
        cudaStreamCreateWithFlags(&g_s2, cudaStreamNonBlocking);
        cudaEventCreateWithFlags(&g_evFork, cudaEventDisableTiming);
        cudaEventCreateWithFlags(&g_evJoin, cudaEventDisableTiming);
    }
} g_streamInit;

// ---------------------------------------------------------------------------
__device__ __forceinline__ uint2 cvt4_f16(float4 v) {
    unsigned xy, zw;
    asm("cvt.rn.f16x2.f32 %0, %1, %2;" : "=r"(xy) : "f"(v.y), "f"(v.x));
    asm("cvt.rn.f16x2.f32 %0, %1, %2;" : "=r"(zw) : "f"(v.w), "f"(v.z));
    return make_uint2(xy, zw);
}

__global__ __launch_bounds__(256)
void prep_kernel(const unsigned long long* __restrict__ s64, int E,
                 const float* __restrict__ W, int M) {
    int i = blockIdx.x * blockDim.x + threadIdx.x;
    // parallel dtype detect: 16 lanes load one u64 each, ballot the high words
    if (blockIdx.x == 0 && threadIdx.x < 32) {
        bool ok = true;
        if (threadIdx.x < 16 && threadIdx.x < E)
            ok = ((s64[threadIdx.x] >> 32) == 0ull);
        unsigned m = __ballot_sync(0xffffffffu, ok);
        if (threadIdx.x == 0) g_idx_is64 = (m == 0xffffffffu) ? 1 : 0;
    }
    if (i < M) { g_count[i] = 0; g_cur[i] = 0; }
    if (i < OUT_F * IN_F / 4) {
        float4 v = *reinterpret_cast<const float4*>(W + (size_t)i * 4);
        uint2 p = cvt4_f16(v);
        *reinterpret_cast<uint2*>(&g_Wh[i * 2]) = p;
    }
}

__device__ __forceinline__ int load_idx(const void* p, int i) {
    if (g_idx_is64) return (int)((const long long*)p)[i];
    return ((const int*)p)[i];
}

__global__ __launch_bounds__(256)
void hist_kernel(const void* __restrict__ dst, int E, int M) {
    int e = blockIdx.x * blockDim.x + threadIdx.x;
    if (e >= E) return;
    int d = load_idx(dst, e);
    if ((unsigned)d < (unsigned)M) atomicAdd(&g_count[d], 1);
}

__global__ __launch_bounds__(SCAN_BLK)
void scan1_kernel(int n) {
    __shared__ int sh[SCAN_BLK];
    int gid = blockIdx.x * SCAN_BLK + threadIdx.x;
    int v = (gid < n) ? g_count[gid] : 0;
    sh[threadIdx.x] = v;
    __syncthreads();
    #pragma unroll
    for (int s = 1; s < SCAN_BLK; s <<= 1) {
        int t = (threadIdx.x >= s) ? sh[threadIdx.x - s] : 0;
        __syncthreads();
        sh[threadIdx.x] += t;
        __syncthreads();
    }
    if (gid < n) g_off[gid] = sh[threadIdx.x] - v;
    if (threadIdx.x == SCAN_BLK - 1) g_blksum[blockIdx.x] = sh[threadIdx.x];
}

__global__ void scan2_kernel(int nblocks) {
    int run = 0;
    for (int i = 0; i < nblocks; i++) {
        int v = g_blksum[i];
        g_blksum[i] = run;
        run += v;
    }
}

__global__ __launch_bounds__(SCAN_BLK)
void scan3_kernel(int n) {
    int gid = blockIdx.x * SCAN_BLK + threadIdx.x;
    if (gid < n) g_off[gid] += g_blksum[blockIdx.x];
}

__global__ __launch_bounds__(256)
void fill_kernel(const void* __restrict__ src, const void* __restrict__ dst,
                 int E, int M) {
    int e = blockIdx.x * blockDim.x + threadIdx.x;
    if (e >= E) return;
    int s = load_idx(src, e);
    int d = load_idx(dst, e);
    if ((unsigned)s >= (unsigned)M || (unsigned)d >= (unsigned)M) return;
    int slot = g_off[d] + atomicAdd(&g_cur[d], 1);
    g_srcs[slot] = s;
}

// ---------------------------------------------------------------------------
// Pull-aggregate, cp.async pipelined (fixed): static warp-per-node, z rows
// staged through a 16-slot smem ring with 8 rows in flight. Row r lives in
// slot r%16; row r is consumed at iter r, slot reused by row r+16 issued at
// iter r+8 (strictly after, program order). Group algebra: row i is in commit
// group i; after iter-i commit there are 9+i groups; wait_group 8 completes
// groups 0..i. Accumulation parity identical to R10 (bitwise-same result).
// ---------------------------------------------------------------------------
__device__ __forceinline__ void cp8_ca(unsigned sdst, const void* gsrc) {
    asm volatile("cp.async.ca.shared.global [%0], [%1], 8;"
                 :: "r"(sdst), "l"(gsrc));
}

__global__ __launch_bounds__(256)
void gather_kernel(const __half* __restrict__ z, float* __restrict__ out, int M) {
    __shared__ __align__(16) char ring[8 * GSLOTS * 256];   // 8 warps x 16 slots x 256B

    int gtid = blockIdx.x * blockDim.x + threadIdx.x;
    int node = gtid >> 5;
    int lane = gtid & 31;
    int wip  = (threadIdx.x >> 5);
    if (node >= M) return;

    char* mybase = ring + wip * GSLOTS * 256 + lane * 8;
    const unsigned myslot0 = (unsigned)__cvta_generic_to_shared(mybase);

    int beg = g_off[node];
    int cnt = g_count[node];

    // prologue: rows 0..7 -> slots 0..7, one commit group per row (groups 0..7)
    #pragma unroll
    for (int j = 0; j < GDEPTH; j++) {
        if (j < cnt) {
            int s = g_srcs[beg + j];
            cp8_ca(myslot0 + (unsigned)(j * 256),
                   z + (size_t)s * OUT_F + lane * 4);
        }
        asm volatile("cp.async.commit_group;");
    }

    float acc0[4] = {}, acc1[4] = {};

    for (int i = 0; i < cnt; i++) {
        // issue row i+8 into slot (i+8)%16 (distinct from slot i%16 read below)
        if (i + GDEPTH < cnt) {
            int s = g_srcs[beg + i + GDEPTH];
            cp8_ca(myslot0 + (unsigned)(((i + GDEPTH) % GSLOTS) * 256),
                   z + (size_t)s * OUT_F + lane * 4);
        }
        asm volatile("cp.async.commit_group;");
        asm volatile("cp.async.wait_group %0;" :: "n"(GDEPTH));  // row i staged

        uint2 u = *reinterpret_cast<uint2*>(mybase + (i % GSLOTS) * 256);
        float2 a = __half22float2(*reinterpret_cast<__half2*>(&u.x));
        float2 b = __half22float2(*reinterpret_cast<__half2*>(&u.y));
        if (i & 1) {
            acc1[0] += a.x; acc1[1] += a.y; acc1[2] += b.x; acc1[3] += b.y;
        } else {
            acc0[0] += a.x; acc0[1] += a.y; acc0[2] += b.x; acc0[3] += b.y;
        }
    }

    float inv = 1.0f / (float)(cnt > 0 ? cnt : 1);
    float4 r;
    r.x = (acc0[0] + acc1[0]) * inv;
    r.y = (acc0[1] + acc1[1]) * inv;
    r.z = (acc0[2] + acc1[2]) * inv;
    r.w = (acc0[3] + acc1[3]) * inv;
    *reinterpret_cast<float4*>(out + (size_t)node * OUT_F + lane * 4) = r;
}

// ---------------------------------------------------------------------------
// Tensor-core GEMM, single-pass fp16 (f32 accum), double-buffered (R10-proven,
// byte-identical).
// ---------------------------------------------------------------------------
#define GBK 32
#define SPAD 40                       // padded fp16 row stride (elements)
#define PLANE (128 * SPAD * 2)        // 10240 bytes
#define STAGE (2 * PLANE)             // 20480 bytes (A + B)
#define OFF_A 0
#define OFF_B PLANE

__device__ __forceinline__ void ldsm_x4(unsigned r[4], unsigned saddr) {
    asm volatile("ldmatrix.sync.aligned.m8n8.x4.shared.b16 {%0,%1,%2,%3}, [%4];"
                 : "=r"(r[0]), "=r"(r[1]), "=r"(r[2]), "=r"(r[3]) : "r"(saddr));
}
__device__ __forceinline__ void mma_f16(float c[4], const unsigned a[4],
                                        const unsigned b[2]) {
    asm volatile("mma.sync.aligned.m16n8k16.row.col.f32.f16.f16.f32 "
                 "{%0,%1,%2,%3}, {%4,%5,%6,%7}, {%8,%9}, {%0,%1,%2,%3};"
                 : "+f"(c[0]), "+f"(c[1]), "+f"(c[2]), "+f"(c[3])
                 : "r"(a[0]), "r"(a[1]), "r"(a[2]), "r"(a[3]),
                   "r"(b[0]), "r"(b[1]));
}
__device__ __forceinline__ void cp16(unsigned sdst, const void* gsrc) {
    asm volatile("cp.async.cg.shared.global [%0], [%1], 16;"
                 :: "r"(sdst), "l"(gsrc));
}

__global__ __launch_bounds__(256, 2)
void gemm_tc_kernel(const float* __restrict__ h, __half* __restrict__ z, int M) {
    extern __shared__ __align__(16) char dyn[];
    const unsigned uDyn = (unsigned)__cvta_generic_to_shared(dyn);

    const int tid  = threadIdx.x;
    const int warp = tid >> 5;
    const int lane = tid & 31;
    const int wm   = warp & 3;
    const int wn   = warp >> 2;
    const int rowBase = blockIdx.x * 128;

    const int ar = tid >> 1;
    const int ac = (tid & 1) * 16;
    const bool aval = (rowBase + ar) < M;
    const float* aptr = h + (size_t)(rowBase + ar) * IN_F + ac;

    const int br = tid >> 1;
    const int bc = (tid & 1) * 8;
    const unsigned bSmemOff = (unsigned)(br * SPAD + bc * 2) * 2u;

    float acc[2][8][4] = {};
    float4 pf[4];

    {
        const unsigned sb = uDyn;
        cp16(sb + OFF_B + bSmemOff,      &g_Wh[(size_t)br * (IN_F / 2) + bc]);
        cp16(sb + OFF_B + bSmemOff + 16, &g_Wh[(size_t)br * (IN_F / 2) + bc + 4]);
        asm volatile("cp.async.commit_group;");
        #pragma unroll
        for (int q = 0; q < 4; q++)
            pf[q] = aval ? *reinterpret_cast<const float4*>(aptr + q * 4)
                         : make_float4(0.f, 0.f, 0.f, 0.f);
        char* ab = dyn;
        #pragma unroll
        for (int q = 0; q < 4; q++) {
            uint2 p = cvt4_f16(pf[q]);
            int o = (ar * SPAD + ac + q * 4) * 2;
            *reinterpret_cast<uint2*>(ab + OFF_A + o) = p;
        }
        asm volatile("cp.async.wait_group 0;");
        __syncthreads();
    }

    const int NCHUNK = IN_F / GBK;   // 8
    for (int c = 0; c < NCHUNK; c++) {
        const int buf  = c & 1;
        const int nbuf = buf ^ 1;
        const unsigned sb  = uDyn + buf * STAGE;
        const unsigned snb = uDyn + nbuf * STAGE;
        const bool has_next = (c + 1 < NCHUNK);

        if (has_next) {
            const int k0n = (c + 1) * GBK;
            cp16(snb + OFF_B + bSmemOff,      &g_Wh[(size_t)br * (IN_F / 2) + k0n / 2 + bc]);
            cp16(snb + OFF_B + bSmemOff + 16, &g_Wh[(size_t)br * (IN_F / 2) + k0n / 2 + bc + 4]);
            asm volatile("cp.async.commit_group;");
            #pragma unroll
            for (int q = 0; q < 4; q++)
                pf[q] = aval ? *reinterpret_cast<const float4*>(aptr + k0n + q * 4)
                             : make_float4(0.f, 0.f, 0.f, 0.f);
        }

        #pragma unroll
        for (int ks = 0; ks < GBK; ks += 16) {
            unsigned a[2][4];
            #pragma unroll
            for (int mt = 0; mt < 2; mt++) {
                int row = wm * 32 + mt * 16 + (lane & 15);
                int col = ks + ((lane >> 4) << 3);
                unsigned off = (unsigned)(row * SPAD + col) * 2u;
                ldsm_x4(a[mt], sb + OFF_A + off);
            }
            #pragma unroll
            for (int np = 0; np < 4; np++) {
                int brow = wn * 64 + np * 16 + ((lane >> 4) << 3) + (lane & 7);
                int bcol = ks + (lane & 8);
                unsigned off = (unsigned)(brow * SPAD + bcol) * 2u;
                unsigned b4[4];
                ldsm_x4(b4, sb + OFF_B + off);
                mma_f16(acc[0][np * 2],     a[0], b4);
                mma_f16(acc[1][np * 2],     a[1], b4);
                mma_f16(acc[0][np * 2 + 1], a[0], b4 + 2);
                mma_f16(acc[1][np * 2 + 1], a[1], b4 + 2);
            }
        }

        if (has_next) {
            char* ab = dyn + nbuf * STAGE;
            #pragma unroll
            for (int q = 0; q < 4; q++) {
                uint2 p = cvt4_f16(pf[q]);
                int o = (ar * SPAD + ac + q * 4) * 2;
                *reinterpret_cast<uint2*>(ab + OFF_A + o) = p;
            }
            asm volatile("cp.async.wait_group 0;");
        }
        __syncthreads();
    }

    const int g   = lane >> 2;
    const int tig = lane & 3;
    #pragma unroll
    for (int mt = 0; mt < 2; mt++) {
        #pragma unroll
        for (int nt = 0; nt < 8; nt++) {
            int row0 = rowBase + wm * 32 + mt * 16 + g;
            int col  = wn * 64 + nt * 8 + tig * 2;
            if (row0 < M) {
                __half2 v = __floats2half2_rn(acc[mt][nt][0], acc[mt][nt][1]);
                *reinterpret_cast<__half2*>(z + (size_t)row0 * OUT_F + col) = v;
            }
            int row1 = row0 + 8;
            if (row1 < M) {
                __half2 v = __floats2half2_rn(acc[mt][nt][2], acc[mt][nt][3]);
                *reinterpret_cast<__half2*>(z + (size_t)row1 * OUT_F + col) = v;
            }
        }
    }
}

// ---------------------------------------------------------------------------
extern "C" void kernel_launch(void* const* d_in, const int* in_sizes, int n_in,
                              void* d_out, int out_size) {
    const float* h   = (const float*)d_in[0];
    const float* W   = (const float*)d_in[1];
    const void*  src = d_in[2];
    const void*  dst = d_in[3];
    float* out = (float*)d_out;

    const int M = in_sizes[0] / IN_F;      // 100000
    const int E = in_sizes[2];             // 1600000

    __half* z;
    cudaGetSymbolAddress((void**)&z, g_z16);

    const int scan_blocks = (M + SCAN_BLK - 1) / SCAN_BLK;   // 98
    const int eb = (E + 255) / 256;                          // 6250
    const int dynBytes = 2 * STAGE;                          // 40960

    cudaFuncSetAttribute(gemm_tc_kernel,
                         cudaFuncAttributeMaxDynamicSharedMemorySize, dynBytes);

    // Launch order: prep(0), hist(1), scan1(2), gemm(3) -> ncu profiles GEMM.
    prep_kernel<<<(M + 255) / 256, 256>>>((const unsigned long long*)src, E, W, M);

    cudaEventRecord(g_evFork, 0);
    cudaStreamWaitEvent(g_s2, g_evFork, 0);

    hist_kernel<<<eb, 256, 0, g_s2>>>(dst, E, M);
    scan1_kernel<<<scan_blocks, SCAN_BLK, 0, g_s2>>>(M);

    gemm_tc_kernel<<<(M + 127) / 128, 256, dynBytes>>>(h, z, M);   // main stream

    scan2_kernel<<<1, 1, 0, g_s2>>>(scan_blocks);
    scan3_kernel<<<scan_blocks, SCAN_BLK, 0, g_s2>>>(M);
    fill_kernel<<<eb, 256, 0, g_s2>>>(src, dst, E, M);

    cudaEventRecord(g_evJoin, g_s2);
    cudaStreamWaitEvent(0, g_evJoin, 0);

    {
        long long threads = (long long)M * 32;
        int blocks = (int)((threads + 255) / 256);   // 12500
        gather_kernel<<<blocks, 256>>>(z, out, M);
    }
}

// round 16
// speedup vs baseline: 1.1803x; 1.1803x over previous
#include <cuda_runtime.h>
#include <cuda_fp16.h>
#include <cstdint>

// GCN layer: out = segment_mean( (h @ W^T)[src], dst )
//   h [100000,256] f32, W [128,256] f32, src/dst [1.6M] idx (dtype runtime-detected)
// fp16 single-pass HMMA GEMM (f32 accum) + fp16 z; CSR build overlapped with GEMM.
// This round: R10 base + unroll-4 gather chains (single-variable change).

#define IN_F  256
#define OUT_F 128
#define MAX_NODES 100000
#define MAX_EDGES 1600000
#define SCAN_BLK  1024

__device__ __half   g_z16[(size_t)MAX_NODES * OUT_F];
__device__ int      g_count[MAX_NODES];
__device__ int      g_off[MAX_NODES];
__device__ int      g_cur[MAX_NODES];
__device__ int      g_srcs[MAX_EDGES];
__device__ int      g_blksum[(MAX_NODES + SCAN_BLK - 1) / SCAN_BLK + 1];
__device__ int      g_idx_is64;
__device__ unsigned g_Wh[OUT_F * IN_F / 2];   // W fp16 plane (packed f16x2)

static cudaStream_t g_s2;
static cudaEvent_t  g_evFork, g_evJoin;
static struct _StreamInit {
    _StreamInit() {
        cudaStreamCreateWithFlags(&g_s2, cudaStreamNonBlocking);
        cudaEventCreateWithFlags(&g_evFork, cudaEventDisableTiming);
        cudaEventCreateWithFlags(&g_evJoin, cudaEventDisableTiming);
    }
} g_streamInit;

// ---------------------------------------------------------------------------
__device__ __forceinline__ uint2 cvt4_f16(float4 v) {
    unsigned xy, zw;
    asm("cvt.rn.f16x2.f32 %0, %1, %2;" : "=r"(xy) : "f"(v.y), "f"(v.x));
    asm("cvt.rn.f16x2.f32 %0, %1, %2;" : "=r"(zw) : "f"(v.w), "f"(v.z));
    return make_uint2(xy, zw);
}

__global__ __launch_bounds__(256)
void prep_kernel(const unsigned long long* __restrict__ s64, int E,
                 const float* __restrict__ W, int M) {
    int i = blockIdx.x * blockDim.x + threadIdx.x;
    // parallel dtype detect (validated R15)
    if (blockIdx.x == 0 && threadIdx.x < 32) {
        bool ok = true;
        if (threadIdx.x < 16 && threadIdx.x < E)
            ok = ((s64[threadIdx.x] >> 32) == 0ull);
        unsigned m = __ballot_sync(0xffffffffu, ok);
        if (threadIdx.x == 0) g_idx_is64 = (m == 0xffffffffu) ? 1 : 0;
    }
    if (i < M) { g_count[i] = 0; g_cur[i] = 0; }
    if (i < OUT_F * IN_F / 4) {
        float4 v = *reinterpret_cast<const float4*>(W + (size_t)i * 4);
        uint2 p = cvt4_f16(v);
        *reinterpret_cast<uint2*>(&g_Wh[i * 2]) = p;
    }
}

__device__ __forceinline__ int load_idx(const void* p, int i) {
    if (g_idx_is64) return (int)((const long long*)p)[i];
    return ((const int*)p)[i];
}

__global__ __launch_bounds__(256)
void hist_kernel(const void* __restrict__ dst, int E, int M) {
    int e = blockIdx.x * blockDim.x + threadIdx.x;
    if (e >= E) return;
    int d = load_idx(dst, e);
    if ((unsigned)d < (unsigned)M) atomicAdd(&g_count[d], 1);
}

__global__ __launch_bounds__(SCAN_BLK)
void scan1_kernel(int n) {
    __shared__ int sh[SCAN_BLK];
    int gid = blockIdx.x * SCAN_BLK + threadIdx.x;
    int v = (gid < n) ? g_count[gid] : 0;
    sh[threadIdx.x] = v;
    __syncthreads();
    #pragma unroll
    for (int s = 1; s < SCAN_BLK; s <<= 1) {
        int t = (threadIdx.x >= s) ? sh[threadIdx.x - s] : 0;
        __syncthreads();
        sh[threadIdx.x] += t;
        __syncthreads();
    }
    if (gid < n) g_off[gid] = sh[threadIdx.x] - v;
    if (threadIdx.x == SCAN_BLK - 1) g_blksum[blockIdx.x] = sh[threadIdx.x];
}

__global__ void scan2_kernel(int nblocks) {
    int run = 0;
    for (int i = 0; i < nblocks; i++) {
        int v = g_blksum[i];
        g_blksum[i] = run;
        run += v;
    }
}

__global__ __launch_bounds__(SCAN_BLK)
void scan3_kernel(int n) {
    int gid = blockIdx.x * SCAN_BLK + threadIdx.x;
    if (gid < n) g_off[gid] += g_blksum[blockIdx.x];
}

__global__ __launch_bounds__(256)
void fill_kernel(const void* __restrict__ src, const void* __restrict__ dst,
                 int E, int M) {
    int e = blockIdx.x * blockDim.x + threadIdx.x;
    if (e >= E) return;
    int s = load_idx(src, e);
    int d = load_idx(dst, e);
    if ((unsigned)s >= (unsigned)M || (unsigned)d >= (unsigned)M) return;
    int slot = g_off[d] + atomicAdd(&g_cur[d], 1);
    g_srcs[slot] = s;
}

// ---------------------------------------------------------------------------
// Pull-aggregate: static warp-per-node (R10-proven scheduling), unroll-4:
// 4 src indices batched, then 4 independent row-load->accumulate chains.
// ---------------------------------------------------------------------------
__global__ __launch_bounds__(256)
void gather_kernel(const __half* __restrict__ z, float* __restrict__ out, int M) {
    int gtid = blockIdx.x * blockDim.x + threadIdx.x;
    int node = gtid >> 5;
    int lane = gtid & 31;
    if (node >= M) return;

    int beg = g_off[node];
    int cnt = g_count[node];

    float a0[4] = {}, a1[4] = {}, a2[4] = {}, a3[4] = {};

    int i = 0;
    for (; i + 4 <= cnt; i += 4) {
        int s0 = g_srcs[beg + i];
        int s1 = g_srcs[beg + i + 1];
        int s2 = g_srcs[beg + i + 2];
        int s3 = g_srcs[beg + i + 3];
        uint2 u0 = *reinterpret_cast<const uint2*>(z + (size_t)s0 * OUT_F + lane * 4);
        uint2 u1 = *reinterpret_cast<const uint2*>(z + (size_t)s1 * OUT_F + lane * 4);
        uint2 u2 = *reinterpret_cast<const uint2*>(z + (size_t)s2 * OUT_F + lane * 4);
        uint2 u3 = *reinterpret_cast<const uint2*>(z + (size_t)s3 * OUT_F + lane * 4);
        float2 p, q;
        p = __half22float2(*reinterpret_cast<__half2*>(&u0.x));
        q = __half22float2(*reinterpret_cast<__half2*>(&u0.y));
        a0[0] += p.x; a0[1] += p.y; a0[2] += q.x; a0[3] += q.y;
        p = __half22float2(*reinterpret_cast<__half2*>(&u1.x));
        q = __half22float2(*reinterpret_cast<__half2*>(&u1.y));
        a1[0] += p.x; a1[1] += p.y; a1[2] += q.x; a1[3] += q.y;
        p = __half22float2(*reinterpret_cast<__half2*>(&u2.x));
        q = __half22float2(*reinterpret_cast<__half2*>(&u2.y));
        a2[0] += p.x; a2[1] += p.y; a2[2] += q.x; a2[3] += q.y;
        p = __half22float2(*reinterpret_cast<__half2*>(&u3.x));
        q = __half22float2(*reinterpret_cast<__half2*>(&u3.y));
        a3[0] += p.x; a3[1] += p.y; a3[2] += q.x; a3[3] += q.y;
    }
    if (i + 2 <= cnt) {
        int s0 = g_srcs[beg + i];
        int s1 = g_srcs[beg + i + 1];
        uint2 u0 = *reinterpret_cast<const uint2*>(z + (size_t)s0 * OUT_F + lane * 4);
        uint2 u1 = *reinterpret_cast<const uint2*>(z + (size_t)s1 * OUT_F + lane * 4);
        float2 p, q;
        p = __half22float2(*reinterpret_cast<__half2*>(&u0.x));
        q = __half22float2(*reinterpret_cast<__half2*>(&u0.y));
        a0[0] += p.x; a0[1] += p.y; a0[2] += q.x; a0[3] += q.y;
        p = __half22float2(*reinterpret_cast<__half2*>(&u1.x));
        q = __half22float2(*reinterpret_cast<__half2*>(&u1.y));
        a1[0] += p.x; a1[1] += p.y; a1[2] += q.x; a1[3] += q.y;
        i += 2;
    }
    if (i < cnt) {
        int s0 = g_srcs[beg + i];
        uint2 u0 = *reinterpret_cast<const uint2*>(z + (size_t)s0 * OUT_F + lane * 4);
        float2 p = __half22float2(*reinterpret_cast<__half2*>(&u0.x));
        float2 q = __half22float2(*reinterpret_cast<__half2*>(&u0.y));
        a0[0] += p.x; a0[1] += p.y; a0[2] += q.x; a0[3] += q.y;
    }

    float inv = 1.0f / (float)(cnt > 0 ? cnt : 1);
    float4 r;
    r.x = ((a0[0] + a1[0]) + (a2[0] + a3[0])) * inv;
    r.y = ((a0[1] + a1[1]) + (a2[1] + a3[1])) * inv;
    r.z = ((a0[2] + a1[2]) + (a2[2] + a3[2])) * inv;
    r.w = ((a0[3] + a1[3]) + (a2[3] + a3[3])) * inv;
    *reinterpret_cast<float4*>(out + (size_t)node * OUT_F + lane * 4) = r;
}

// ---------------------------------------------------------------------------
// Tensor-core GEMM, single-pass fp16 (f32 accum), double-buffered (R10-proven,
// byte-identical).
// ---------------------------------------------------------------------------
#define GBK 32
#define SPAD 40                       // padded fp16 row stride (elements)
#define PLANE (128 * SPAD * 2)        // 10240 bytes
#define STAGE (2 * PLANE)             // 20480 bytes (A + B)
#define OFF_A 0
#define OFF_B PLANE

__device__ __forceinline__ void ldsm_x4(unsigned r[4], unsigned saddr) {
    asm volatile("ldmatrix.sync.aligned.m8n8.x4.shared.b16 {%0,%1,%2,%3}, [%4];"
                 : "=r"(r[0]), "=r"(r[1]), "=r"(r[2]), "=r"(r[3]) : "r"(saddr));
}
__device__ __forceinline__ void mma_f16(float c[4], const unsigned a[4],
                                        const unsigned b[2]) {
    asm volatile("mma.sync.aligned.m16n8k16.row.col.f32.f16.f16.f32 "
                 "{%0,%1,%2,%3}, {%4,%5,%6,%7}, {%8,%9}, {%0,%1,%2,%3};"
                 : "+f"(c[0]), "+f"(c[1]), "+f"(c[2]), "+f"(c[3])
                 : "r"(a[0]), "r"(a[1]), "r"(a[2]), "r"(a[3]),
                   "r"(b[0]), "r"(b[1]));
}
__device__ __forceinline__ void cp16(unsigned sdst, const void* gsrc) {
    asm volatile("cp.async.cg.shared.global [%0], [%1], 16;"
                 :: "r"(sdst), "l"(gsrc));
}

__global__ __launch_bounds__(256, 2)
void gemm_tc_kernel(const float* __restrict__ h, __half* __restrict__ z, int M) {
    extern __shared__ __align__(16) char dyn[];
    const unsigned uDyn = (unsigned)__cvta_generic_to_shared(dyn);

    const int tid  = threadIdx.x;
    const int warp = tid >> 5;
    const int lane = tid & 31;
    const int wm   = warp & 3;
    const int wn   = warp >> 2;
    const int rowBase = blockIdx.x * 128;

    const int ar = tid >> 1;
    const int ac = (tid & 1) * 16;
    const bool aval = (rowBase + ar) < M;
    const float* aptr = h + (size_t)(rowBase + ar) * IN_F + ac;

    const int br = tid >> 1;
    const int bc = (tid & 1) * 8;
    const unsigned bSmemOff = (unsigned)(br * SPAD + bc * 2) * 2u;

    float acc[2][8][4] = {};
    float4 pf[4];

    {
        const unsigned sb = uDyn;
        cp16(sb + OFF_B + bSmemOff,      &g_Wh[(size_t)br * (IN_F / 2) + bc]);
        cp16(sb + OFF_B + bSmemOff + 16, &g_Wh[(size_t)br * (IN_F / 2) + bc + 4]);
        asm volatile("cp.async.commit_group;");
        #pragma unroll
        for (int q = 0; q < 4; q++)
            pf[q] = aval ? *reinterpret_cast<const float4*>(aptr + q * 4)
                         : make_float4(0.f, 0.f, 0.f, 0.f);
        char* ab = dyn;
        #pragma unroll
        for (int q = 0; q < 4; q++) {
            uint2 p = cvt4_f16(pf[q]);
            int o = (ar * SPAD + ac + q * 4) * 2;
            *reinterpret_cast<uint2*>(ab + OFF_A + o) = p;
        }
        asm volatile("cp.async.wait_group 0;");
        __syncthreads();
    }

    const int NCHUNK = IN_F / GBK;   // 8
    for (int c = 0; c < NCHUNK; c++) {
        const int buf  = c & 1;
        const int nbuf = buf ^ 1;
        const unsigned sb  = uDyn + buf * STAGE;
        const unsigned snb = uDyn + nbuf * STAGE;
        const bool has_next = (c + 1 < NCHUNK);

        if (has_next) {
            const int k0n = (c + 1) * GBK;
            cp16(snb + OFF_B + bSmemOff,      &g_Wh[(size_t)br * (IN_F / 2) + k0n / 2 + bc]);
            cp16(snb + OFF_B + bSmemOff + 16, &g_Wh[(size_t)br * (IN_F / 2) + k0n / 2 + bc + 4]);
            asm volatile("cp.async.commit_group;");
            #pragma unroll
            for (int q = 0; q < 4; q++)
                pf[q] = aval ? *reinterpret_cast<const float4*>(aptr + k0n + q * 4)
                             : make_float4(0.f, 0.f, 0.f, 0.f);
        }

        #pragma unroll
        for (int ks = 0; ks < GBK; ks += 16) {
            unsigned a[2][4];
            #pragma unroll
            for (int mt = 0; mt < 2; mt++) {
                int row = wm * 32 + mt * 16 + (lane & 15);
                int col = ks + ((lane >> 4) << 3);
                unsigned off = (unsigned)(row * SPAD + col) * 2u;
                ldsm_x4(a[mt], sb + OFF_A + off);
            }
            #pragma unroll
            for (int np = 0; np < 4; np++) {
                int brow = wn * 64 + np * 16 + ((lane >> 4) << 3) + (lane & 7);
                int bcol = ks + (lane & 8);
                unsigned off = (unsigned)(brow * SPAD + bcol) * 2u;
                unsigned b4[4];
                ldsm_x4(b4, sb + OFF_B + off);
                mma_f16(acc[0][np * 2],     a[0], b4);
                mma_f16(acc[1][np * 2],     a[1], b4);
                mma_f16(acc[0][np * 2 + 1], a[0], b4 + 2);
                mma_f16(acc[1][np * 2 + 1], a[1], b4 + 2);
            }
        }

        if (has_next) {
            char* ab = dyn + nbuf * STAGE;
            #pragma unroll
            for (int q = 0; q < 4; q++) {
                uint2 p = cvt4_f16(pf[q]);
                int o = (ar * SPAD + ac + q * 4) * 2;
                *reinterpret_cast<uint2*>(ab + OFF_A + o) = p;
            }
            asm volatile("cp.async.wait_group 0;");
        }
        __syncthreads();
    }

    const int g   = lane >> 2;
    const int tig = lane & 3;
    #pragma unroll
    for (int mt = 0; mt < 2; mt++) {
        #pragma unroll
        for (int nt = 0; nt < 8; nt++) {
            int row0 = rowBase + wm * 32 + mt * 16 + g;
            int col  = wn * 64 + nt * 8 + tig * 2;
            if (row0 < M) {
                __half2 v = __floats2half2_rn(acc[mt][nt][0], acc[mt][nt][1]);
                *reinterpret_cast<__half2*>(z + (size_t)row0 * OUT_F + col) = v;
            }
            int row1 = row0 + 8;
            if (row1 < M) {
                __half2 v = __floats2half2_rn(acc[mt][nt][2], acc[mt][nt][3]);
                *reinterpret_cast<__half2*>(z + (size_t)row1 * OUT_F + col) = v;
            }
        }
    }
}

// ---------------------------------------------------------------------------
extern "C" void kernel_launch(void* const* d_in, const int* in_sizes, int n_in,
                              void* d_out, int out_size) {
    const float* h   = (const float*)d_in[0];
    const float* W   = (const float*)d_in[1];
    const void*  src = d_in[2];
    const void*  dst = d_in[3];
    float* out = (float*)d_out;

    const int M = in_sizes[0] / IN_F;      // 100000
    const int E = in_sizes[2];             // 1600000

    __half* z;
    cudaGetSymbolAddress((void**)&z, g_z16);

    const int scan_blocks = (M + SCAN_BLK - 1) / SCAN_BLK;   // 98
    const int eb = (E + 255) / 256;                          // 6250
    const int dynBytes = 2 * STAGE;                          // 40960

    cudaFuncSetAttribute(gemm_tc_kernel,
                         cudaFuncAttributeMaxDynamicSharedMemorySize, dynBytes);

    prep_kernel<<<(M + 255) / 256, 256>>>((const unsigned long long*)src, E, W, M);

    cudaEventRecord(g_evFork, 0);
    cudaStreamWaitEvent(g_s2, g_evFork, 0);

    gemm_tc_kernel<<<(M + 127) / 128, 256, dynBytes>>>(h, z, M);

    hist_kernel<<<eb, 256, 0, g_s2>>>(dst, E, M);
    scan1_kernel<<<scan_blocks, SCAN_BLK, 0, g_s2>>>(M);
    scan2_kernel<<<1, 1, 0, g_s2>>>(scan_blocks);
    scan3_kernel<<<scan_blocks, SCAN_BLK, 0, g_s2>>>(M);
    fill_kernel<<<eb, 256, 0, g_s2>>>(src, dst, E, M);

    cudaEventRecord(g_evJoin, g_s2);
    cudaStreamWaitEvent(0, g_evJoin, 0);

    {
        long long threads = (long long)M * 32;
        int blocks = (int)((threads + 255) / 256);   // 12500
        gather_kernel<<<blocks, 256>>>(z, out, M);
    }
}